// round 14
// baseline (speedup 1.0000x reference)
#include <cuda_runtime.h>
#include <cuda_bf16.h>
#include <cstdint>

#define NN 16
#define KK 4
#define BB 16384
#define DD 64
#define FINAL_ID 15
#define BSTRIDE 712      // 704 + 8 pad (bf16 elems per B-image row)

// ---------------- scratch (__device__ globals; no allocs) -------------------
__device__ uint2    g_packed[NN * BB];              // spike bitmasks
__device__ unsigned g_xhi[BB * 32];                 // bf16x2 pairs of hi(inputs)
__device__ unsigned g_xlo[BB * 32];                 // bf16x2 pairs of lo(inputs)
__device__ unsigned short g_Bimg[NN * 64 * BSTRIDE];// B image [n][c][k]

// ---------------------------------------------------------------------------
// Kernel 0: pack s_prev (binary 0/1 floats) into bitmasks.
// ---------------------------------------------------------------------------
__global__ void pack_kernel(const float* __restrict__ s_prev) {
    const int ROWS_PER_WARP = 8;
    int warp = (blockIdx.x * blockDim.x + threadIdx.x) >> 5;
    int lane = threadIdx.x & 31;
    int row0 = warp * ROWS_PER_WARP;
    #pragma unroll
    for (int r = 0; r < ROWS_PER_WARP; r++) {
        int row = row0 + r;
        float v0 = s_prev[(size_t)row * DD + lane];
        float v1 = s_prev[(size_t)row * DD + 32 + lane];
        unsigned lo = __ballot_sync(0xffffffffu, v0 != 0.0f);
        unsigned hi = __ballot_sync(0xffffffffu, v1 != 0.0f);
        if (lane == 0) g_packed[row] = make_uint2(lo, hi);
    }
}

// ---------------------------------------------------------------------------
// Kernel 1: split inputs into bf16 hi/lo pairs (packed bf16x2, even col low).
// ---------------------------------------------------------------------------
__global__ void prep_x_kernel(const float* __restrict__ inputs) {
    int idx = blockIdx.x * blockDim.x + threadIdx.x;   // 0 .. BB*32-1
    float x0 = inputs[idx * 2], x1 = inputs[idx * 2 + 1];
    __nv_bfloat16 h0 = __float2bfloat16(x0), h1 = __float2bfloat16(x1);
    float r0 = x0 - __bfloat162float(h0);
    float r1 = x1 - __bfloat162float(h1);
    __nv_bfloat16 l0 = __float2bfloat16(r0), l1 = __float2bfloat16(r1);
    unsigned short b0 = *(unsigned short*)&h0, b1 = *(unsigned short*)&h1;
    unsigned short c0 = *(unsigned short*)&l0, c1 = *(unsigned short*)&l1;
    g_xhi[idx] = ((unsigned)b1 << 16) | b0;
    g_xlo[idx] = ((unsigned)c1 << 16) | c0;
}

// ---------------------------------------------------------------------------
// Kernel 2: build B image [n][c][k], k-major rows per output col c.
// k 0..255   : hi(Ws[k][c])     k 256..319: hi(Wd[k][c])
// k 320..383 : hi(Wd[k-64][c])  k 384..639: lo(Ws[k-384][c])
// k 640..703 : lo(Wd[k-384][c])
// ---------------------------------------------------------------------------
__global__ void prep_w_kernel(const float* __restrict__ W) {
    int n = blockIdx.x >> 6, c = blockIdx.x & 63;
    const float* Wn = W + (size_t)n * 320 * 64;
    for (int k = threadIdx.x; k < 704; k += 256) {
        unsigned short bits;
        if (k < 384) {
            int i = (k < 320) ? k : k - 64;
            __nv_bfloat16 h = __float2bfloat16(Wn[i * 64 + c]);
            bits = *(unsigned short*)&h;
        } else {
            int j = k - 384;                   // 0..319
            float v = Wn[j * 64 + c];
            __nv_bfloat16 h = __float2bfloat16(v);
            float r = v - __bfloat162float(h);
            __nv_bfloat16 l = __float2bfloat16(r);
            bits = *(unsigned short*)&l;
        }
        g_Bimg[(size_t)(n * 64 + c) * BSTRIDE + k] = bits;
    }
}

// ---------------- warp MMA helpers -----------------------------------------
__device__ __forceinline__ uint32_t smem_u32(const void* p) {
    uint32_t a;
    asm("{ .reg .u64 t; cvta.to.shared.u64 t, %1; cvt.u32.u64 %0, t; }"
        : "=r"(a) : "l"(p));
    return a;
}
__device__ __forceinline__ void mma16816(float* c, uint32_t a0, uint32_t a1,
                                         uint32_t a2, uint32_t a3,
                                         uint32_t b0, uint32_t b1) {
    asm volatile(
        "mma.sync.aligned.m16n8k16.row.col.f32.bf16.bf16.f32 "
        "{%0,%1,%2,%3}, {%4,%5,%6,%7}, {%8,%9}, {%0,%1,%2,%3};"
        : "+f"(c[0]), "+f"(c[1]), "+f"(c[2]), "+f"(c[3])
        : "r"(a0), "r"(a1), "r"(a2), "r"(a3), "r"(b0), "r"(b1));
}
__device__ __forceinline__ void ldm4(uint32_t& b0, uint32_t& b1,
                                     uint32_t& b2, uint32_t& b3, uint32_t addr) {
    asm volatile("ldmatrix.sync.aligned.m8n8.x4.shared.b16 {%0,%1,%2,%3}, [%4];"
                 : "=r"(b0), "=r"(b1), "=r"(b2), "=r"(b3) : "r"(addr));
}
// 2-bit spike pair -> packed bf16x2 {bit0 -> 1.0 low, bit1 -> 1.0 high}
__device__ __forceinline__ uint32_t p2b(unsigned p) {
    return (p & 1u) * 0x3F80u + (p >> 1) * 0x3F800000u;
}

// ---------------------------------------------------------------------------
// Kernel 3: split-bf16 HMMA GEMM + LIF epilogue, warp-pair N-split.
// Block = 256 thr (8 warps = 4 pairs), covers 128 batch rows of one node.
// Pair owns 32 rows; within a pair, nside=0 computes cols 0..31, nside=1
// cols 32..63. Each warp: 2 M-tiles x 4 N-tiles; B frags loaded once per kc
// (2 ldm.x4) and reused for both M-tiles -> ldmatrix traffic halved vs R9.
// ---------------------------------------------------------------------------
__global__ __launch_bounds__(256, 2)
void snn_mma_kernel(const float* __restrict__ u,
                    const float* __restrict__ i_syn,
                    const float* __restrict__ bias,
                    const int*   __restrict__ conn,
                    float* __restrict__ out) {
    extern __shared__ unsigned short Bs[];          // [64][BSTRIDE]
    const int tid = threadIdx.x;
    const int w = tid >> 5, lane = tid & 31;
    const int n = blockIdx.x, tile = blockIdx.y;

    // copy pre-built B image into smem (89 KB, uint4)
    {
        const uint4* src = (const uint4*)(g_Bimg + (size_t)n * 64 * BSTRIDE);
        uint4* dst = (uint4*)Bs;
        for (int i = tid; i < 64 * BSTRIDE / 8; i += 256) dst[i] = src[i];
    }
    __syncthreads();

    const int gr = lane >> 2, tg = lane & 3;
    const int pairid = w >> 1, nside = w & 1;
    const int rbase = tile * 128 + pairid * 32;

    // masks for both M-tiles (rows rbase + m*16 + gr, +8)
    uint2 ml[2][4], mh[2][4];
    #pragma unroll
    for (int m = 0; m < 2; m++) {
        const int r0 = rbase + m * 16 + gr;
        #pragma unroll
        for (int k = 0; k < 4; k++) {
            int s = __ldg(conn + n * KK + k);
            ml[m][k] = g_packed[s * BB + r0];
            mh[m][k] = g_packed[s * BB + r0 + 8];
        }
    }

    float acc[2][4][4];
    #pragma unroll
    for (int m = 0; m < 2; m++)
        #pragma unroll
        for (int nt = 0; nt < 4; nt++)
            #pragma unroll
            for (int q = 0; q < 4; q++) acc[m][nt][q] = 0.0f;

    const uint32_t sbase = smem_u32(Bs);
    const int lrow = (lane & 7) + ((lane >> 4) & 1) * 8;
    const int lkof = ((lane >> 3) & 1) * 8;
    const int brow = nside * 32;

    // ---- pass 1: K cols 0..383 (spike-hi, x_hi*Wd_hi, x_lo*Wd_hi) ----
    #pragma unroll
    for (int kc = 0; kc < 24; kc++) {
        const int k0 = kc * 16;
        uint32_t b[2][4];
        #pragma unroll
        for (int np = 0; np < 2; np++) {
            uint32_t addr = sbase +
                ((brow + np * 16 + lrow) * BSTRIDE + k0 + lkof) * 2;
            ldm4(b[np][0], b[np][1], b[np][2], b[np][3], addr);
        }
        #pragma unroll
        for (int m = 0; m < 2; m++) {
            const int r0 = rbase + m * 16 + gr;
            uint32_t a0, a1, a2, a3;
            if (kc < 16) {
                const int s = kc >> 2, q = kc & 3;
                unsigned fl = ((q & 2) ? ml[m][s].y : ml[m][s].x) >> ((q & 1) * 16);
                unsigned fh = ((q & 2) ? mh[m][s].y : mh[m][s].x) >> ((q & 1) * 16);
                a0 = p2b((fl >> (2 * tg)) & 3);
                a1 = p2b((fh >> (2 * tg)) & 3);
                a2 = p2b((fl >> (2 * tg + 8)) & 3);
                a3 = p2b((fh >> (2 * tg + 8)) & 3);
            } else if (kc < 20) {
                const int j = kc - 16;
                a0 = __ldg(g_xhi + r0 * 32 + j * 8 + tg);
                a2 = __ldg(g_xhi + r0 * 32 + j * 8 + tg + 4);
                a1 = __ldg(g_xhi + (r0 + 8) * 32 + j * 8 + tg);
                a3 = __ldg(g_xhi + (r0 + 8) * 32 + j * 8 + tg + 4);
            } else {
                const int j = kc - 20;
                a0 = __ldg(g_xlo + r0 * 32 + j * 8 + tg);
                a2 = __ldg(g_xlo + r0 * 32 + j * 8 + tg + 4);
                a1 = __ldg(g_xlo + (r0 + 8) * 32 + j * 8 + tg);
                a3 = __ldg(g_xlo + (r0 + 8) * 32 + j * 8 + tg + 4);
            }
            #pragma unroll
            for (int np = 0; np < 2; np++) {
                mma16816(acc[m][2 * np],     a0, a1, a2, a3, b[np][0], b[np][1]);
                mma16816(acc[m][2 * np + 1], a0, a1, a2, a3, b[np][2], b[np][3]);
            }
        }
    }

    // ---- pass 2: K cols 384..703 (spike-lo, x_hi*Wd_lo) ----
    #pragma unroll
    for (int kc = 0; kc < 20; kc++) {
        const int k0 = 384 + kc * 16;
        uint32_t b[2][4];
        #pragma unroll
        for (int np = 0; np < 2; np++) {
            uint32_t addr = sbase +
                ((brow + np * 16 + lrow) * BSTRIDE + k0 + lkof) * 2;
            ldm4(b[np][0], b[np][1], b[np][2], b[np][3], addr);
        }
        #pragma unroll
        for (int m = 0; m < 2; m++) {
            const int r0 = rbase + m * 16 + gr;
            uint32_t a0, a1, a2, a3;
            if (kc < 16) {
                const int s = kc >> 2, q = kc & 3;
                unsigned fl = ((q & 2) ? ml[m][s].y : ml[m][s].x) >> ((q & 1) * 16);
                unsigned fh = ((q & 2) ? mh[m][s].y : mh[m][s].x) >> ((q & 1) * 16);
                a0 = p2b((fl >> (2 * tg)) & 3);
                a1 = p2b((fh >> (2 * tg)) & 3);
                a2 = p2b((fl >> (2 * tg + 8)) & 3);
                a3 = p2b((fh >> (2 * tg + 8)) & 3);
            } else {
                const int j = kc - 16;
                a0 = __ldg(g_xhi + r0 * 32 + j * 8 + tg);
                a2 = __ldg(g_xhi + r0 * 32 + j * 8 + tg + 4);
                a1 = __ldg(g_xhi + (r0 + 8) * 32 + j * 8 + tg);
                a3 = __ldg(g_xhi + (r0 + 8) * 32 + j * 8 + tg + 4);
            }
            #pragma unroll
            for (int np = 0; np < 2; np++) {
                mma16816(acc[m][2 * np],     a0, a1, a2, a3, b[np][0], b[np][1]);
                mma16816(acc[m][2 * np + 1], a0, a1, a2, a3, b[np][2], b[np][3]);
            }
        }
    }

    // ---- LIF epilogue ----
    float* s_out = out + (size_t)BB * DD;
    float* u_out = s_out + (size_t)NN * BB * DD;
    float* i_out = u_out + (size_t)NN * BB * DD;

    #pragma unroll
    for (int m = 0; m < 2; m++) {
        #pragma unroll
        for (int nt = 0; nt < 4; nt++) {
            const int c = nside * 32 + nt * 8 + 2 * tg;
            const float2 bb = __ldg((const float2*)(bias + n * DD + c));
            #pragma unroll
            for (int h = 0; h < 2; h++) {
                const int row = rbase + m * 16 + gr + h * 8;
                const size_t base = ((size_t)(n * BB) + row) * DD + c;
                float2 uu = *(const float2*)(u + base);
                float2 ii = *(const float2*)(i_syn + base);
                float ax = acc[m][nt][2 * h]     + bb.x;
                float ay = acc[m][nt][2 * h + 1] + bb.y;

                float inx = fmaf(0.9f, ii.x, ax);
                float iny = fmaf(0.9f, ii.y, ay);
                float unx = fmaf(0.95f, uu.x, 0.05f * inx);
                float uny = fmaf(0.95f, uu.y, 0.05f * iny);
                float svx = (unx - 1.0f > 0.0f) ? 1.0f : 0.0f;
                float svy = (uny - 1.0f > 0.0f) ? 1.0f : 0.0f;
                float2 sv = make_float2(svx, svy);
                float2 uo = make_float2(svx > 0.5f ? 0.0f : unx,
                                        svy > 0.5f ? 0.0f : uny);
                float2 iv = make_float2(inx, iny);

                *(float2*)(s_out + base) = sv;
                *(float2*)(u_out + base) = uo;
                *(float2*)(i_out + base) = iv;
                if (n == FINAL_ID)
                    *(float2*)(out + (size_t)row * DD + c) = sv;
            }
        }
    }
}

// ---------------------------------------------------------------------------
extern "C" void kernel_launch(void* const* d_in, const int* in_sizes, int n_in,
                              void* d_out, int out_size) {
    const float* inputs = (const float*)d_in[0];
    const float* u      = (const float*)d_in[1];
    const float* i_syn  = (const float*)d_in[2];
    const float* s_prev = (const float*)d_in[3];
    const float* W      = (const float*)d_in[4];
    const float* bias   = (const float*)d_in[5];
    const int*   conn   = (const int*)d_in[6];
    float* out = (float*)d_out;

    pack_kernel<<<(NN * BB) / 64, 256>>>(s_prev);
    prep_x_kernel<<<(BB * 32) / 256, 256>>>(inputs);
    prep_w_kernel<<<NN * 64, 256>>>(W);

    const int smem = 64 * BSTRIDE * 2;              // 91,136 B
    cudaFuncSetAttribute(snn_mma_kernel,
                         cudaFuncAttributeMaxDynamicSharedMemorySize, smem);
    dim3 grid(NN, BB / 128);
    snn_mma_kernel<<<grid, 256, smem>>>(u, i_syn, bias, conn, out);
}

// round 17
// speedup vs baseline: 1.4680x; 1.4680x over previous
#include <cuda_runtime.h>
#include <cuda_bf16.h>
#include <cstdint>

#define NN 16
#define KK 4
#define BB 16384
#define DD 64
#define FINAL_ID 15
#define BSTRIDE 712      // 704 + 8 pad (bf16 elems per B-image row)
#define TILES_PER_BLOCK 2

// ---------------- scratch (__device__ globals; no allocs) -------------------
__device__ uint2    g_packed[NN * BB];              // spike bitmasks
__device__ unsigned g_xhi[BB * 32];                 // bf16x2 pairs of hi(inputs)
__device__ unsigned g_xlo[BB * 32];                 // bf16x2 pairs of lo(inputs)
__device__ unsigned short g_Bimg[NN * 64 * BSTRIDE];// B image [n][c][k]

// ---------------------------------------------------------------------------
// Kernel 0: pack s_prev (binary 0/1 floats) into bitmasks.
// ---------------------------------------------------------------------------
__global__ void pack_kernel(const float* __restrict__ s_prev) {
    const int ROWS_PER_WARP = 8;
    int warp = (blockIdx.x * blockDim.x + threadIdx.x) >> 5;
    int lane = threadIdx.x & 31;
    int row0 = warp * ROWS_PER_WARP;
    #pragma unroll
    for (int r = 0; r < ROWS_PER_WARP; r++) {
        int row = row0 + r;
        float v0 = s_prev[(size_t)row * DD + lane];
        float v1 = s_prev[(size_t)row * DD + 32 + lane];
        unsigned lo = __ballot_sync(0xffffffffu, v0 != 0.0f);
        unsigned hi = __ballot_sync(0xffffffffu, v1 != 0.0f);
        if (lane == 0) g_packed[row] = make_uint2(lo, hi);
    }
}

// ---------------------------------------------------------------------------
// Kernel 1: split inputs into bf16 hi/lo pairs (packed bf16x2, even col low).
// ---------------------------------------------------------------------------
__global__ void prep_x_kernel(const float* __restrict__ inputs) {
    int idx = blockIdx.x * blockDim.x + threadIdx.x;   // 0 .. BB*32-1
    float x0 = inputs[idx * 2], x1 = inputs[idx * 2 + 1];
    __nv_bfloat16 h0 = __float2bfloat16(x0), h1 = __float2bfloat16(x1);
    float r0 = x0 - __bfloat162float(h0);
    float r1 = x1 - __bfloat162float(h1);
    __nv_bfloat16 l0 = __float2bfloat16(r0), l1 = __float2bfloat16(r1);
    unsigned short b0 = *(unsigned short*)&h0, b1 = *(unsigned short*)&h1;
    unsigned short c0 = *(unsigned short*)&l0, c1 = *(unsigned short*)&l1;
    g_xhi[idx] = ((unsigned)b1 << 16) | b0;
    g_xlo[idx] = ((unsigned)c1 << 16) | c0;
}

// ---------------------------------------------------------------------------
// Kernel 2: build B image [n][c][k], k-major rows per output col c.
// k 0..255   : hi(Ws[k][c])     k 256..319: hi(Wd[k][c])
// k 320..383 : hi(Wd[k-64][c])  k 384..639: lo(Ws[k-384][c])
// k 640..703 : lo(Wd[k-384][c])
// ---------------------------------------------------------------------------
__global__ void prep_w_kernel(const float* __restrict__ W) {
    int n = blockIdx.x >> 6, c = blockIdx.x & 63;
    const float* Wn = W + (size_t)n * 320 * 64;
    for (int k = threadIdx.x; k < 704; k += 256) {
        unsigned short bits;
        if (k < 384) {
            int i = (k < 320) ? k : k - 64;
            __nv_bfloat16 h = __float2bfloat16(Wn[i * 64 + c]);
            bits = *(unsigned short*)&h;
        } else {
            int j = k - 384;                   // 0..319
            float v = Wn[j * 64 + c];
            __nv_bfloat16 h = __float2bfloat16(v);
            float r = v - __bfloat162float(h);
            __nv_bfloat16 l = __float2bfloat16(r);
            bits = *(unsigned short*)&l;
        }
        g_Bimg[(size_t)(n * 64 + c) * BSTRIDE + k] = bits;
    }
}

// ---------------- warp MMA helpers -----------------------------------------
__device__ __forceinline__ uint32_t smem_u32(const void* p) {
    uint32_t a;
    asm("{ .reg .u64 t; cvta.to.shared.u64 t, %1; cvt.u32.u64 %0, t; }"
        : "=r"(a) : "l"(p));
    return a;
}
__device__ __forceinline__ void mma16816(float* c, uint32_t a0, uint32_t a1,
                                         uint32_t a2, uint32_t a3,
                                         uint32_t b0, uint32_t b1) {
    asm volatile(
        "mma.sync.aligned.m16n8k16.row.col.f32.bf16.bf16.f32 "
        "{%0,%1,%2,%3}, {%4,%5,%6,%7}, {%8,%9}, {%0,%1,%2,%3};"
        : "+f"(c[0]), "+f"(c[1]), "+f"(c[2]), "+f"(c[3])
        : "r"(a0), "r"(a1), "r"(a2), "r"(a3), "r"(b0), "r"(b1));
}
__device__ __forceinline__ void ldm4(uint32_t& b0, uint32_t& b1,
                                     uint32_t& b2, uint32_t& b3, uint32_t addr) {
    asm volatile("ldmatrix.sync.aligned.m8n8.x4.shared.b16 {%0,%1,%2,%3}, [%4];"
                 : "=r"(b0), "=r"(b1), "=r"(b2), "=r"(b3) : "r"(addr));
}
// 2-bit spike pair -> packed bf16x2 {bit0 -> 1.0 low, bit1 -> 1.0 high}
__device__ __forceinline__ uint32_t p2b(unsigned p) {
    return (p & 1u) * 0x3F80u + (p >> 1) * 0x3F800000u;
}

// ---------------------------------------------------------------------------
// Kernel 3: split-bf16 HMMA GEMM + LIF epilogue (R9 layout), 2 tiles/block.
// 256 threads = 8 warps; warp owns 16 batch rows x all 64 out cols.
// B tile (64x704 bf16, stride 712) loaded ONCE per block via cp.async and
// reused across TILES_PER_BLOCK row-tiles.
// ---------------------------------------------------------------------------
__global__ __launch_bounds__(256, 2)
void snn_mma_kernel(const float* __restrict__ u,
                    const float* __restrict__ i_syn,
                    const float* __restrict__ bias,
                    const int*   __restrict__ conn,
                    float* __restrict__ out) {
    extern __shared__ unsigned short Bs[];          // [64][BSTRIDE]
    const int tid = threadIdx.x;
    const int w = tid >> 5, lane = tid & 31;
    const int n = blockIdx.x;

    // copy pre-built B image into smem via cp.async (bypasses L1 + RF)
    {
        const uint4* src = (const uint4*)(g_Bimg + (size_t)n * 64 * BSTRIDE);
        const uint32_t dbase = smem_u32(Bs);
        for (int i = tid; i < 64 * BSTRIDE / 8; i += 256) {
            uint32_t d = dbase + i * 16;
            asm volatile("cp.async.cg.shared.global [%0], [%1], 16;"
                         :: "r"(d), "l"(src + i));
        }
        asm volatile("cp.async.commit_group;");
        asm volatile("cp.async.wait_group 0;" ::: "memory");
    }
    __syncthreads();

    const int gr = lane >> 2, tg = lane & 3;
    const uint32_t sbase = smem_u32(Bs);
    const int lrow = (lane & 7) + ((lane >> 4) & 1) * 8; // row in 16-row npair
    const int lkof = ((lane >> 3) & 1) * 8;              // k offset 0/8

    float* s_out = out + (size_t)BB * DD;
    float* u_out = s_out + (size_t)NN * BB * DD;
    float* i_out = u_out + (size_t)NN * BB * DD;

    #pragma unroll 1
    for (int t = 0; t < TILES_PER_BLOCK; t++) {
        const int tile = blockIdx.y * TILES_PER_BLOCK + t;
        const int rbase = tile * 128 + w * 16;
        const int row0 = rbase + gr, row1 = row0 + 8;

        uint2 ml[4], mh[4];
        #pragma unroll
        for (int k = 0; k < 4; k++) {
            int s = __ldg(conn + n * KK + k);
            ml[k] = g_packed[s * BB + row0];
            mh[k] = g_packed[s * BB + row1];
        }

        float acc[8][4];
        #pragma unroll
        for (int nt = 0; nt < 8; nt++)
            #pragma unroll
            for (int q = 0; q < 4; q++) acc[nt][q] = 0.0f;

        // ---- pass 1: K cols 0..383 (spike-hi, x_hi*Wd_hi, x_lo*Wd_hi) ----
        #pragma unroll
        for (int kc = 0; kc < 24; kc++) {
            uint32_t a0, a1, a2, a3;
            if (kc < 16) {
                const int s = kc >> 2, q = kc & 3;
                unsigned fl = ((q & 2) ? ml[s].y : ml[s].x) >> ((q & 1) * 16);
                unsigned fh = ((q & 2) ? mh[s].y : mh[s].x) >> ((q & 1) * 16);
                a0 = p2b((fl >> (2 * tg)) & 3);
                a1 = p2b((fh >> (2 * tg)) & 3);
                a2 = p2b((fl >> (2 * tg + 8)) & 3);
                a3 = p2b((fh >> (2 * tg + 8)) & 3);
            } else if (kc < 20) {
                const int j = kc - 16;
                a0 = __ldg(g_xhi + row0 * 32 + j * 8 + tg);
                a2 = __ldg(g_xhi + row0 * 32 + j * 8 + tg + 4);
                a1 = __ldg(g_xhi + row1 * 32 + j * 8 + tg);
                a3 = __ldg(g_xhi + row1 * 32 + j * 8 + tg + 4);
            } else {
                const int j = kc - 20;
                a0 = __ldg(g_xlo + row0 * 32 + j * 8 + tg);
                a2 = __ldg(g_xlo + row0 * 32 + j * 8 + tg + 4);
                a1 = __ldg(g_xlo + row1 * 32 + j * 8 + tg);
                a3 = __ldg(g_xlo + row1 * 32 + j * 8 + tg + 4);
            }
            const int k0 = kc * 16;
            #pragma unroll
            for (int np = 0; np < 4; np++) {
                uint32_t b0, b1, b2, b3;
                uint32_t addr = sbase + ((np * 16 + lrow) * BSTRIDE + k0 + lkof) * 2;
                ldm4(b0, b1, b2, b3, addr);
                mma16816(acc[2 * np],     a0, a1, a2, a3, b0, b1);
                mma16816(acc[2 * np + 1], a0, a1, a2, a3, b2, b3);
            }
        }

        // ---- pass 2: K cols 384..703 (spike-lo, x_hi*Wd_lo) ----
        #pragma unroll
        for (int kc = 0; kc < 20; kc++) {
            uint32_t a0, a1, a2, a3;
            if (kc < 16) {
                const int s = kc >> 2, q = kc & 3;
                unsigned fl = ((q & 2) ? ml[s].y : ml[s].x) >> ((q & 1) * 16);
                unsigned fh = ((q & 2) ? mh[s].y : mh[s].x) >> ((q & 1) * 16);
                a0 = p2b((fl >> (2 * tg)) & 3);
                a1 = p2b((fh >> (2 * tg)) & 3);
                a2 = p2b((fl >> (2 * tg + 8)) & 3);
                a3 = p2b((fh >> (2 * tg + 8)) & 3);
            } else {
                const int j = kc - 16;
                a0 = __ldg(g_xhi + row0 * 32 + j * 8 + tg);
                a2 = __ldg(g_xhi + row0 * 32 + j * 8 + tg + 4);
                a1 = __ldg(g_xhi + row1 * 32 + j * 8 + tg);
                a3 = __ldg(g_xhi + row1 * 32 + j * 8 + tg + 4);
            }
            const int k0 = 384 + kc * 16;
            #pragma unroll
            for (int np = 0; np < 4; np++) {
                uint32_t b0, b1, b2, b3;
                uint32_t addr = sbase + ((np * 16 + lrow) * BSTRIDE + k0 + lkof) * 2;
                ldm4(b0, b1, b2, b3, addr);
                mma16816(acc[2 * np],     a0, a1, a2, a3, b0, b1);
                mma16816(acc[2 * np + 1], a0, a1, a2, a3, b2, b3);
            }
        }

        // ---- LIF epilogue: thread owns rows {row0,row1} x cols {nt*8+2tg,+1}
        #pragma unroll
        for (int nt = 0; nt < 8; nt++) {
            const int c = nt * 8 + 2 * tg;
            const float2 bb = __ldg((const float2*)(bias + n * DD + c));
            #pragma unroll
            for (int h = 0; h < 2; h++) {
                const int row = h ? row1 : row0;
                const size_t base = ((size_t)(n * BB) + row) * DD + c;
                float2 uu = *(const float2*)(u + base);
                float2 ii = *(const float2*)(i_syn + base);
                float ax = acc[nt][2 * h]     + bb.x;
                float ay = acc[nt][2 * h + 1] + bb.y;

                float inx = fmaf(0.9f, ii.x, ax);
                float iny = fmaf(0.9f, ii.y, ay);
                float unx = fmaf(0.95f, uu.x, 0.05f * inx);
                float uny = fmaf(0.95f, uu.y, 0.05f * iny);
                float svx = (unx - 1.0f > 0.0f) ? 1.0f : 0.0f;
                float svy = (uny - 1.0f > 0.0f) ? 1.0f : 0.0f;
                float2 sv = make_float2(svx, svy);
                float2 uo = make_float2(svx > 0.5f ? 0.0f : unx,
                                        svy > 0.5f ? 0.0f : uny);
                float2 iv = make_float2(inx, iny);

                *(float2*)(s_out + base) = sv;
                *(float2*)(u_out + base) = uo;
                *(float2*)(i_out + base) = iv;
                if (n == FINAL_ID)
                    *(float2*)(out + (size_t)row * DD + c) = sv;
            }
        }
    }
}

// ---------------------------------------------------------------------------
extern "C" void kernel_launch(void* const* d_in, const int* in_sizes, int n_in,
                              void* d_out, int out_size) {
    const float* inputs = (const float*)d_in[0];
    const float* u      = (const float*)d_in[1];
    const float* i_syn  = (const float*)d_in[2];
    const float* s_prev = (const float*)d_in[3];
    const float* W      = (const float*)d_in[4];
    const float* bias   = (const float*)d_in[5];
    const int*   conn   = (const int*)d_in[6];
    float* out = (float*)d_out;

    pack_kernel<<<(NN * BB) / 64, 256>>>(s_prev);
    prep_x_kernel<<<(BB * 32) / 256, 256>>>(inputs);
    prep_w_kernel<<<NN * 64, 256>>>(W);

    const int smem = 64 * BSTRIDE * 2;              // 91,136 B
    cudaFuncSetAttribute(snn_mma_kernel,
                         cudaFuncAttributeMaxDynamicSharedMemorySize, smem);
    dim3 grid(NN, (BB / 128) / TILES_PER_BLOCK);
    snn_mma_kernel<<<grid, 256, smem>>>(u, i_syn, bias, conn, out);
}